// round 2
// baseline (speedup 1.0000x reference)
#include <cuda_runtime.h>

#define E_DIM 1024
#define SEQ   2048
#define NH    16
#define HD    64
#define MTOK  4096            // B*S
#define ATT_SCALE 0.125f      // 64^-0.5

// Scratch (allocation-free rule): Q,K,V projections and attention context.
__device__ float g_q[(size_t)MTOK * E_DIM];
__device__ float g_k[(size_t)MTOK * E_DIM];
__device__ float g_v[(size_t)MTOK * E_DIM];
__device__ float g_ctx[(size_t)MTOK * E_DIM];

// ---------------------------------------------------------------------------
// SGEMM: C[M,N] = A[M,K] * W[N,K]^T + bias[N],  M=4096, N=K=1024
// Tile 128x128x16, 256 threads, 8x8 per thread.
// ---------------------------------------------------------------------------
__device__ __forceinline__ void gemm_body(const float* __restrict__ A,
                                          const float* __restrict__ W,
                                          const float* __restrict__ bias,
                                          float* __restrict__ C)
{
    __shared__ float As[16][128];
    __shared__ float Ws[16][128];

    const int tid  = threadIdx.x;
    const int row0 = blockIdx.y * 128;
    const int col0 = blockIdx.x * 128;

    const int lr  = tid >> 2;          // 0..63  (load row)
    const int lc  = (tid & 3) << 2;    // 0,4,8,12 (load k-col, float4)
    const int tRow = (tid >> 4) << 3;  // 0..120 step 8
    const int tCol = (tid & 15) << 3;  // 0..120 step 8

    float acc[8][8];
#pragma unroll
    for (int i = 0; i < 8; i++)
#pragma unroll
        for (int j = 0; j < 8; j++) acc[i][j] = 0.f;

    const float* Ab = A + (size_t)row0 * E_DIM;
    const float* Wb = W + (size_t)col0 * E_DIM;

    for (int k0 = 0; k0 < E_DIM; k0 += 16) {
#pragma unroll
        for (int h = 0; h < 2; h++) {
            const int rr = lr + h * 64;
            float4 a4 = *(const float4*)(Ab + (size_t)rr * E_DIM + k0 + lc);
            As[lc + 0][rr] = a4.x; As[lc + 1][rr] = a4.y;
            As[lc + 2][rr] = a4.z; As[lc + 3][rr] = a4.w;
            float4 w4 = *(const float4*)(Wb + (size_t)rr * E_DIM + k0 + lc);
            Ws[lc + 0][rr] = w4.x; Ws[lc + 1][rr] = w4.y;
            Ws[lc + 2][rr] = w4.z; Ws[lc + 3][rr] = w4.w;
        }
        __syncthreads();
#pragma unroll
        for (int kk = 0; kk < 16; kk++) {
            float ra[8], rb[8];
            *(float4*)&ra[0] = *(float4*)&As[kk][tRow];
            *(float4*)&ra[4] = *(float4*)&As[kk][tRow + 4];
            *(float4*)&rb[0] = *(float4*)&Ws[kk][tCol];
            *(float4*)&rb[4] = *(float4*)&Ws[kk][tCol + 4];
#pragma unroll
            for (int i = 0; i < 8; i++)
#pragma unroll
                for (int j = 0; j < 8; j++)
                    acc[i][j] += ra[i] * rb[j];
        }
        __syncthreads();
    }

#pragma unroll
    for (int i = 0; i < 8; i++) {
#pragma unroll
        for (int j = 0; j < 8; j += 4) {
            float4 o;
            o.x = acc[i][j + 0] + bias[col0 + tCol + j + 0];
            o.y = acc[i][j + 1] + bias[col0 + tCol + j + 1];
            o.z = acc[i][j + 2] + bias[col0 + tCol + j + 2];
            o.w = acc[i][j + 3] + bias[col0 + tCol + j + 3];
            *(float4*)&C[(size_t)(row0 + tRow + i) * E_DIM + col0 + tCol + j] = o;
        }
    }
}

__global__ void __launch_bounds__(256)
k_gemm_qkv(const float* __restrict__ A,
           const float* __restrict__ wq, const float* __restrict__ bq,
           const float* __restrict__ wk, const float* __restrict__ bk,
           const float* __restrict__ wv, const float* __restrict__ bv)
{
    const float *W, *bias;
    float* C;
    if (blockIdx.z == 0)      { W = wq; bias = bq; C = g_q; }
    else if (blockIdx.z == 1) { W = wk; bias = bk; C = g_k; }
    else                      { W = wv; bias = bv; C = g_v; }
    gemm_body(A, W, bias, C);
}

__global__ void __launch_bounds__(256)
k_gemm_out(const float* __restrict__ wo, const float* __restrict__ bo,
           float* __restrict__ Cout)
{
    gemm_body(g_ctx, wo, bo, Cout);
}

// ---------------------------------------------------------------------------
// Flash attention, fp32. One CTA = one (b, h, 64-query tile).
// 256 threads: thread = (row r in 0..63, colgroup cg in 0..3 -> 16 cols/dims).
// smem: Qs[64][68], Ks[64][68] (reused as P), Vs[64][68]  = 52224 B dynamic.
// ---------------------------------------------------------------------------
#define FPAD 68

__global__ void __launch_bounds__(256) k_flash()
{
    extern __shared__ float sm[];
    float* Qs = sm;
    float* Ks = sm + 64 * FPAD;   // reused as P after scores
    float* Vs = sm + 2 * 64 * FPAD;

    const int tid = threadIdx.x;
    const int qt = blockIdx.x, h = blockIdx.y, b = blockIdx.z;
    const size_t base = (size_t)b * SEQ * E_DIM + (size_t)h * HD;

    // load Q tile (64 rows x 64 d)
    for (int i = tid; i < 64 * 16; i += 256) {
        const int rr = i >> 4, c4 = (i & 15) << 2;
        *(float4*)&Qs[rr * FPAD + c4] =
            *(const float4*)&g_q[base + (size_t)(qt * 64 + rr) * E_DIM + c4];
    }

    const int r  = tid >> 2;
    const int c0 = (tid & 3) << 4;

    float m_i = -3.0e38f, l_i = 0.f;
    float oa[16];
#pragma unroll
    for (int j = 0; j < 16; j++) oa[j] = 0.f;

    __syncthreads();

    for (int kt = 0; kt < SEQ / 64; kt++) {
        // load K,V tiles
        for (int i = tid; i < 64 * 16; i += 256) {
            const int rr = i >> 4, c4 = (i & 15) << 2;
            const size_t g = base + (size_t)(kt * 64 + rr) * E_DIM + c4;
            *(float4*)&Ks[rr * FPAD + c4] = *(const float4*)&g_k[g];
            *(float4*)&Vs[rr * FPAD + c4] = *(const float4*)&g_v[g];
        }
        __syncthreads();

        // scores s[j] = Q[r] . K[c0+j]
        float s[16];
#pragma unroll
        for (int j = 0; j < 16; j++) s[j] = 0.f;
#pragma unroll
        for (int d4 = 0; d4 < 64; d4 += 4) {
            const float4 q4 = *(float4*)&Qs[r * FPAD + d4];
#pragma unroll
            for (int j = 0; j < 16; j++) {
                const float4 k4 = *(float4*)&Ks[(c0 + j) * FPAD + d4];
                s[j] += q4.x * k4.x + q4.y * k4.y + q4.z * k4.z + q4.w * k4.w;
            }
        }

        // online softmax (row split across 4 lanes -> shfl reduce)
        float mloc = s[0];
#pragma unroll
        for (int j = 1; j < 16; j++) mloc = fmaxf(mloc, s[j]);
        mloc = fmaxf(mloc, __shfl_xor_sync(0xffffffffu, mloc, 1));
        mloc = fmaxf(mloc, __shfl_xor_sync(0xffffffffu, mloc, 2));
        const float m_new = fmaxf(m_i, mloc * ATT_SCALE);
        const float alpha = __expf(m_i - m_new);
        float lloc = 0.f;
#pragma unroll
        for (int j = 0; j < 16; j++) {
            const float p = __expf(s[j] * ATT_SCALE - m_new);
            s[j] = p;
            lloc += p;
        }
        lloc += __shfl_xor_sync(0xffffffffu, lloc, 1);
        lloc += __shfl_xor_sync(0xffffffffu, lloc, 2);
        l_i = l_i * alpha + lloc;
        m_i = m_new;
#pragma unroll
        for (int j = 0; j < 16; j++) oa[j] *= alpha;

        __syncthreads();  // everyone done reading Ks as K
        // write P into Ks
#pragma unroll
        for (int j4 = 0; j4 < 16; j4 += 4)
            *(float4*)&Ks[r * FPAD + c0 + j4] =
                make_float4(s[j4], s[j4 + 1], s[j4 + 2], s[j4 + 3]);
        __syncthreads();

        // O[r][c0..c0+15] += P[r][:] @ V[:][c0..c0+15]
        for (int c4 = 0; c4 < 64; c4 += 4) {
            const float4 p4 = *(float4*)&Ks[r * FPAD + c4];
            const float pv[4] = {p4.x, p4.y, p4.z, p4.w};
#pragma unroll
            for (int cc = 0; cc < 4; cc++) {
#pragma unroll
                for (int j4 = 0; j4 < 16; j4 += 4) {
                    const float4 v4 = *(float4*)&Vs[(c4 + cc) * FPAD + c0 + j4];
                    oa[j4 + 0] += pv[cc] * v4.x;
                    oa[j4 + 1] += pv[cc] * v4.y;
                    oa[j4 + 2] += pv[cc] * v4.z;
                    oa[j4 + 3] += pv[cc] * v4.w;
                }
            }
        }
        __syncthreads();
    }

    const float inv = 1.0f / l_i;
#pragma unroll
    for (int j4 = 0; j4 < 16; j4 += 4) {
        const float4 o4 = make_float4(oa[j4] * inv, oa[j4 + 1] * inv,
                                      oa[j4 + 2] * inv, oa[j4 + 3] * inv);
        *(float4*)&g_ctx[base + (size_t)(qt * 64 + r) * E_DIM + c0 + j4] = o4;
    }
}

// ---------------------------------------------------------------------------

extern "C" void kernel_launch(void* const* d_in, const int* in_sizes, int n_in,
                              void* d_out, int out_size)
{
    const float* x  = (const float*)d_in[0];
    const float* qw = (const float*)d_in[1];
    const float* qb = (const float*)d_in[2];
    const float* kw = (const float*)d_in[3];
    const float* kb = (const float*)d_in[4];
    const float* vw = (const float*)d_in[5];
    const float* vb = (const float*)d_in[6];
    const float* ow = (const float*)d_in[7];
    const float* ob = (const float*)d_in[8];
    float* out = (float*)d_out;

    const int flash_smem = 3 * 64 * FPAD * (int)sizeof(float);  // 52224
    cudaFuncSetAttribute(k_flash, cudaFuncAttributeMaxDynamicSharedMemorySize,
                         flash_smem);

    dim3 gq(E_DIM / 128, MTOK / 128, 3);
    k_gemm_qkv<<<gq, 256>>>(x, qw, qb, kw, kb, vw, vb);

    dim3 gf(SEQ / 64, NH, 2);
    k_flash<<<gf, 256, flash_smem>>>();

    dim3 go(E_DIM / 128, MTOK / 128, 1);
    k_gemm_out<<<go, 256>>>(ow, ob, out);
}

// round 3
// speedup vs baseline: 9.0123x; 9.0123x over previous
#include <cuda_runtime.h>

#define E_DIM 1024
#define SEQ   2048
#define NH    16
#define HD    64
#define MTOK  4096
#define ATT_SCALE 0.125f

__device__ float g_q[(size_t)MTOK * E_DIM];
__device__ float g_k[(size_t)MTOK * E_DIM];
__device__ float g_v[(size_t)MTOK * E_DIM];
__device__ float g_ctx[(size_t)MTOK * E_DIM];

__device__ __forceinline__ unsigned f2tf(float x) {
    unsigned r;
    asm("cvt.rna.tf32.f32 %0, %1;" : "=r"(r) : "f"(x));
    return r;
}

__device__ __forceinline__ void mma_tf32(float* c, const unsigned* a,
                                         unsigned b0, unsigned b1) {
    asm volatile(
        "mma.sync.aligned.m16n8k8.row.col.f32.tf32.tf32.f32 "
        "{%0,%1,%2,%3}, {%4,%5,%6,%7}, {%8,%9}, {%0,%1,%2,%3};\n"
        : "+f"(c[0]), "+f"(c[1]), "+f"(c[2]), "+f"(c[3])
        : "r"(a[0]), "r"(a[1]), "r"(a[2]), "r"(a[3]), "r"(b0), "r"(b1));
}

// ---------------------------------------------------------------------------
// tf32 GEMM: C[M,N] = A[M,K] * W[N,K]^T + bias.  Tile 128x128x16, 256 thr.
// 8 warps (4 x 2): each warp 32 rows x 64 cols = 2 x 8 m16n8k8 tiles.
// ---------------------------------------------------------------------------
#define GS 20   // smem row stride (floats): frag banks 20g+tig distinct

__device__ __forceinline__ void gemm_body(const float* __restrict__ A,
                                          const float* __restrict__ W,
                                          const float* __restrict__ bias,
                                          float* __restrict__ C)
{
    __shared__ unsigned As[128 * GS];
    __shared__ unsigned Ws[128 * GS];

    const int tid  = threadIdx.x;
    const int lane = tid & 31, warp = tid >> 5;
    const int g = lane >> 2, tig = lane & 3;
    const int m0 = (warp >> 1) * 32;
    const int n0 = (warp & 1) * 64;
    const int row0 = blockIdx.y * 128;
    const int col0 = blockIdx.x * 128;

    const int lr = tid >> 2;           // 0..63
    const int lc = (tid & 3) << 2;     // 0,4,8,12

    float acc[2][8][4];
#pragma unroll
    for (int mi = 0; mi < 2; mi++)
#pragma unroll
        for (int ni = 0; ni < 8; ni++)
#pragma unroll
            for (int j = 0; j < 4; j++) acc[mi][ni][j] = 0.f;

    const float* Ab = A + (size_t)row0 * E_DIM;
    const float* Wb = W + (size_t)col0 * E_DIM;

    for (int k0 = 0; k0 < E_DIM; k0 += 16) {
#pragma unroll
        for (int h = 0; h < 2; h++) {
            const int rr = lr + h * 64;
            float4 a4 = *(const float4*)(Ab + (size_t)rr * E_DIM + k0 + lc);
            As[rr * GS + lc + 0] = f2tf(a4.x);
            As[rr * GS + lc + 1] = f2tf(a4.y);
            As[rr * GS + lc + 2] = f2tf(a4.z);
            As[rr * GS + lc + 3] = f2tf(a4.w);
            float4 w4 = *(const float4*)(Wb + (size_t)rr * E_DIM + k0 + lc);
            Ws[rr * GS + lc + 0] = f2tf(w4.x);
            Ws[rr * GS + lc + 1] = f2tf(w4.y);
            Ws[rr * GS + lc + 2] = f2tf(w4.z);
            Ws[rr * GS + lc + 3] = f2tf(w4.w);
        }
        __syncthreads();

#pragma unroll
        for (int kk = 0; kk < 16; kk += 8) {
            unsigned a[2][4], bf[8][2];
#pragma unroll
            for (int mi = 0; mi < 2; mi++) {
                const int row = m0 + mi * 16;
                a[mi][0] = As[(row + g) * GS + kk + tig];
                a[mi][1] = As[(row + g + 8) * GS + kk + tig];
                a[mi][2] = As[(row + g) * GS + kk + tig + 4];
                a[mi][3] = As[(row + g + 8) * GS + kk + tig + 4];
            }
#pragma unroll
            for (int ni = 0; ni < 8; ni++) {
                const int col = n0 + ni * 8;
                bf[ni][0] = Ws[(col + g) * GS + kk + tig];
                bf[ni][1] = Ws[(col + g) * GS + kk + tig + 4];
            }
#pragma unroll
            for (int mi = 0; mi < 2; mi++)
#pragma unroll
                for (int ni = 0; ni < 8; ni++)
                    mma_tf32(acc[mi][ni], a[mi], bf[ni][0], bf[ni][1]);
        }
        __syncthreads();
    }

#pragma unroll
    for (int mi = 0; mi < 2; mi++) {
#pragma unroll
        for (int ni = 0; ni < 8; ni++) {
            const int row = row0 + m0 + mi * 16;
            const int col = col0 + n0 + ni * 8 + 2 * tig;
            const float bx = bias[col], by = bias[col + 1];
            float2 r0 = make_float2(acc[mi][ni][0] + bx, acc[mi][ni][1] + by);
            float2 r1 = make_float2(acc[mi][ni][2] + bx, acc[mi][ni][3] + by);
            *(float2*)&C[(size_t)(row + g) * E_DIM + col] = r0;
            *(float2*)&C[(size_t)(row + g + 8) * E_DIM + col] = r1;
        }
    }
}

__global__ void __launch_bounds__(256)
k_gemm_qkv(const float* __restrict__ A,
           const float* __restrict__ wq, const float* __restrict__ bq,
           const float* __restrict__ wk, const float* __restrict__ bk,
           const float* __restrict__ wv, const float* __restrict__ bv)
{
    const float *W, *bias;
    float* C;
    if (blockIdx.z == 0)      { W = wq; bias = bq; C = g_q; }
    else if (blockIdx.z == 1) { W = wk; bias = bk; C = g_k; }
    else                      { W = wv; bias = bv; C = g_v; }
    gemm_body(A, W, bias, C);
}

__global__ void __launch_bounds__(256)
k_gemm_out(const float* __restrict__ wo, const float* __restrict__ bo,
           float* __restrict__ Cout)
{
    gemm_body(g_ctx, wo, bo, Cout);
}

// ---------------------------------------------------------------------------
// Flash attention tf32. CTA = (b, h, 64-query tile), 128 thr = 4 warps.
// Warp w owns query rows w*16..w*16+15. Q frags in regs; K/V/P in smem.
// ---------------------------------------------------------------------------
#define FS 68   // smem row stride (elems); frag banks 4g+tig distinct

__global__ void __launch_bounds__(128) k_flash()
{
    extern __shared__ unsigned sm[];
    unsigned* Ks = sm;                 // 64 x FS
    unsigned* Vs = sm + 64 * FS;       // 64 x FS
    unsigned* Ps = sm + 2 * 64 * FS;   // 64 x FS (Q staging, then P)

    const int tid  = threadIdx.x;
    const int lane = tid & 31, warp = tid >> 5;
    const int g = lane >> 2, tig = lane & 3;
    const int qt = blockIdx.x, h = blockIdx.y, b = blockIdx.z;
    const size_t base = (size_t)b * SEQ * E_DIM + (size_t)h * HD;
    const int wr = warp * 16;

    // stage Q (64 x 64) into Ps, cvt tf32
    for (int i = tid; i < 64 * 16; i += 128) {
        const int rr = i >> 4, c4 = (i & 15) << 2;
        float4 q4 = *(const float4*)&g_q[base + (size_t)(qt * 64 + rr) * E_DIM + c4];
        Ps[rr * FS + c4 + 0] = f2tf(q4.x);
        Ps[rr * FS + c4 + 1] = f2tf(q4.y);
        Ps[rr * FS + c4 + 2] = f2tf(q4.z);
        Ps[rr * FS + c4 + 3] = f2tf(q4.w);
    }
    __syncthreads();

    // Q fragments: 8 k-steps (d), resident for whole kernel
    unsigned qa[8][4];
#pragma unroll
    for (int ks = 0; ks < 8; ks++) {
        qa[ks][0] = Ps[(wr + g) * FS + 8 * ks + tig];
        qa[ks][1] = Ps[(wr + g + 8) * FS + 8 * ks + tig];
        qa[ks][2] = Ps[(wr + g) * FS + 8 * ks + tig + 4];
        qa[ks][3] = Ps[(wr + g + 8) * FS + 8 * ks + tig + 4];
    }
    __syncthreads();

    float o[8][4];
#pragma unroll
    for (int ni = 0; ni < 8; ni++)
#pragma unroll
        for (int j = 0; j < 4; j++) o[ni][j] = 0.f;
    float m0 = -3.0e38f, m1 = -3.0e38f, l0 = 0.f, l1 = 0.f;

    for (int kt = 0; kt < SEQ / 64; kt++) {
        // load K,V tile (64 x 64), cvt tf32
        for (int i = tid; i < 64 * 16; i += 128) {
            const int rr = i >> 4, c4 = (i & 15) << 2;
            const size_t gaddr = base + (size_t)(kt * 64 + rr) * E_DIM + c4;
            float4 k4 = *(const float4*)&g_k[gaddr];
            Ks[rr * FS + c4 + 0] = f2tf(k4.x);
            Ks[rr * FS + c4 + 1] = f2tf(k4.y);
            Ks[rr * FS + c4 + 2] = f2tf(k4.z);
            Ks[rr * FS + c4 + 3] = f2tf(k4.w);
            float4 v4 = *(const float4*)&g_v[gaddr];
            Vs[rr * FS + c4 + 0] = f2tf(v4.x);
            Vs[rr * FS + c4 + 1] = f2tf(v4.y);
            Vs[rr * FS + c4 + 2] = f2tf(v4.z);
            Vs[rr * FS + c4 + 3] = f2tf(v4.w);
        }
        __syncthreads();

        // S = Q K^T : warp computes 16 x 64 scores = 8 n-tiles
        float s[8][4];
#pragma unroll
        for (int ni = 0; ni < 8; ni++)
#pragma unroll
            for (int j = 0; j < 4; j++) s[ni][j] = 0.f;
#pragma unroll
        for (int ks = 0; ks < 8; ks++) {
#pragma unroll
            for (int ni = 0; ni < 8; ni++) {
                unsigned b0 = Ks[(8 * ni + g) * FS + 8 * ks + tig];
                unsigned b1 = Ks[(8 * ni + g) * FS + 8 * ks + tig + 4];
                mma_tf32(s[ni], qa[ks], b0, b1);
            }
        }

        // scale + online softmax (rows g and g+8 per thread)
        float mx0 = -3.0e38f, mx1 = -3.0e38f;
#pragma unroll
        for (int ni = 0; ni < 8; ni++) {
            s[ni][0] *= ATT_SCALE; s[ni][1] *= ATT_SCALE;
            s[ni][2] *= ATT_SCALE; s[ni][3] *= ATT_SCALE;
            mx0 = fmaxf(mx0, fmaxf(s[ni][0], s[ni][1]));
            mx1 = fmaxf(mx1, fmaxf(s[ni][2], s[ni][3]));
        }
        mx0 = fmaxf(mx0, __shfl_xor_sync(0xffffffffu, mx0, 1));
        mx0 = fmaxf(mx0, __shfl_xor_sync(0xffffffffu, mx0, 2));
        mx1 = fmaxf(mx1, __shfl_xor_sync(0xffffffffu, mx1, 1));
        mx1 = fmaxf(mx1, __shfl_xor_sync(0xffffffffu, mx1, 2));
        const float mn0 = fmaxf(m0, mx0), mn1 = fmaxf(m1, mx1);
        const float al0 = __expf(m0 - mn0), al1 = __expf(m1 - mn1);
        float s0 = 0.f, s1 = 0.f;
#pragma unroll
        for (int ni = 0; ni < 8; ni++) {
            float p0 = __expf(s[ni][0] - mn0);
            float p1 = __expf(s[ni][1] - mn0);
            float p2 = __expf(s[ni][2] - mn1);
            float p3 = __expf(s[ni][3] - mn1);
            s0 += p0 + p1; s1 += p2 + p3;
            // P -> smem (own warp rows only)
            uint2 w0 = make_uint2(f2tf(p0), f2tf(p1));
            uint2 w1 = make_uint2(f2tf(p2), f2tf(p3));
            *(uint2*)&Ps[(wr + g) * FS + 8 * ni + 2 * tig] = w0;
            *(uint2*)&Ps[(wr + g + 8) * FS + 8 * ni + 2 * tig] = w1;
        }
        s0 += __shfl_xor_sync(0xffffffffu, s0, 1);
        s0 += __shfl_xor_sync(0xffffffffu, s0, 2);
        s1 += __shfl_xor_sync(0xffffffffu, s1, 1);
        s1 += __shfl_xor_sync(0xffffffffu, s1, 2);
        l0 = l0 * al0 + s0;
        l1 = l1 * al1 + s1;
        m0 = mn0; m1 = mn1;
#pragma unroll
        for (int ni = 0; ni < 8; ni++) {
            o[ni][0] *= al0; o[ni][1] *= al0;
            o[ni][2] *= al1; o[ni][3] *= al1;
        }
        __syncwarp();

        // O += P V : k-dim = 64 tokens (8 steps), n = 64 head dims (8 tiles)
#pragma unroll
        for (int ks = 0; ks < 8; ks++) {
            unsigned pa[4];
            pa[0] = Ps[(wr + g) * FS + 8 * ks + tig];
            pa[1] = Ps[(wr + g + 8) * FS + 8 * ks + tig];
            pa[2] = Ps[(wr + g) * FS + 8 * ks + tig + 4];
            pa[3] = Ps[(wr + g + 8) * FS + 8 * ks + tig + 4];
#pragma unroll
            for (int ni = 0; ni < 8; ni++) {
                unsigned b0 = Vs[(8 * ks + tig) * FS + 8 * ni + g];
                unsigned b1 = Vs[(8 * ks + tig + 4) * FS + 8 * ni + g];
                mma_tf32(o[ni], pa, b0, b1);
            }
        }
        __syncthreads();
    }

    const float i0 = 1.0f / l0, i1 = 1.0f / l1;
    const int grow = qt * 64 + wr;
#pragma unroll
    for (int ni = 0; ni < 8; ni++) {
        const int col = 8 * ni + 2 * tig;
        float2 r0 = make_float2(o[ni][0] * i0, o[ni][1] * i0);
        float2 r1 = make_float2(o[ni][2] * i1, o[ni][3] * i1);
        *(float2*)&g_ctx[base + (size_t)(grow + g) * E_DIM + col] = r0;
        *(float2*)&g_ctx[base + (size_t)(grow + g + 8) * E_DIM + col] = r1;
    }
}

// ---------------------------------------------------------------------------

extern "C" void kernel_launch(void* const* d_in, const int* in_sizes, int n_in,
                              void* d_out, int out_size)
{
    const float* x  = (const float*)d_in[0];
    const float* qw = (const float*)d_in[1];
    const float* qb = (const float*)d_in[2];
    const float* kw = (const float*)d_in[3];
    const float* kb = (const float*)d_in[4];
    const float* vw = (const float*)d_in[5];
    const float* vb = (const float*)d_in[6];
    const float* ow = (const float*)d_in[7];
    const float* ob = (const float*)d_in[8];
    float* out = (float*)d_out;

    const int flash_smem = 3 * 64 * FS * (int)sizeof(unsigned);  // 52224
    cudaFuncSetAttribute(k_flash, cudaFuncAttributeMaxDynamicSharedMemorySize,
                         flash_smem);

    dim3 gq(E_DIM / 128, MTOK / 128, 3);
    k_gemm_qkv<<<gq, 256>>>(x, qw, qb, kw, kb, vw, vb);

    dim3 gf(SEQ / 64, NH, 2);
    k_flash<<<gf, 256 / 2, flash_smem>>>();

    dim3 go(E_DIM / 128, MTOK / 128, 1);
    k_gemm_out<<<go, 256>>>(ow, ob, out);
}